// round 13
// baseline (speedup 1.0000x reference)
#include <cuda_runtime.h>
#include <cstdint>

#define N_TOK   4096
#define C_DIM   64
#define HW      256
#define E_EXP   16
#define CCAP    384
#define PLANE   (E_EXP * CCAP)             /* 6144 */
#define HALF    ((long long)N_TOK * PLANE) /* 25,165,824 floats */
#define NBIN    32
#define TPB     4                           /* tokens per pool block */

// ---------------- device scratch (bins reset each replay by k_finish blk 0) --------
__device__ float g_gate[N_TOK];
__device__ int   g_arg[N_TOK];
__device__ float g_psumb[NBIN * E_EXP];   // binned prob sums (bin-major)
__device__ float g_zsumb[NBIN];           // binned lse sums

// =====================================================================
// K1: pure-read pool, 4 tokens per block. grid = 1024 x 512.
// =====================================================================
__global__ void __launch_bounds__(512, 4)
k_pool(const float* __restrict__ X, const float* __restrict__ Wg,
       const float* __restrict__ bg) {
    const int n0   = blockIdx.x * TPB;
    const int tid  = threadIdx.x;
    const int w    = tid >> 5;
    const int lane = tid & 31;

    __shared__ float s_ch[TPB][C_DIM];
    __shared__ float s_w[C_DIM * E_EXP];

    for (int i = tid; i < C_DIM * E_EXP; i += 512) s_w[i] = Wg[i];

    // warp w owns channels [4w, 4w+4) of each token; lanes consecutive -> coalesced
#pragma unroll
    for (int t = 0; t < TPB; t++) {
        const float4* p = reinterpret_cast<const float4*>(
                              X + (size_t)(n0 + t) * C_DIM * HW) + w * 256;
        float part[4] = {0.f, 0.f, 0.f, 0.f};
#pragma unroll
        for (int k = 0; k < 8; k++) {
            float4 v = __ldcs(p + lane + 32 * k);
            part[k >> 1] += (v.x + v.y) + (v.z + v.w);
        }
#pragma unroll
        for (int c = 0; c < 4; c++) {
            float s = part[c];
#pragma unroll
            for (int off = 16; off; off >>= 1) s += __shfl_xor_sync(0xffffffffu, s, off);
            if (lane == 0) s_ch[t][4 * w + c] = s * (1.0f / HW);
        }
    }
    __syncthreads();

    // epilogue: warp t handles token n0+t (4 softmaxes in parallel)
    if (w < TPB) {
        const int n = n0 + w;
        float l = -INFINITY;
        if (lane < E_EXP) {
            float acc = bg[lane];
#pragma unroll
            for (int c = 0; c < C_DIM; c++) acc += s_ch[w][c] * s_w[c * E_EXP + lane];
            l = acc;
        }
        float mx = l;
#pragma unroll
        for (int off = 16; off; off >>= 1) mx = fmaxf(mx, __shfl_xor_sync(0xffffffffu, mx, off));
        float e = (lane < E_EXP) ? __expf(l - mx) : 0.f;
        float s = e;
#pragma unroll
        for (int off = 16; off; off >>= 1) s += __shfl_xor_sync(0xffffffffu, s, off);
        float prob = e / s;
        float lse  = mx + __logf(s);

        unsigned bal = __ballot_sync(0xffffffffu, l == mx);
        int arg = __ffs(bal) - 1;                   // lowest-index max == jnp argmax
        float gate = __shfl_sync(0xffffffffu, prob, arg);

        const int bin = n & (NBIN - 1);             // spread atomic contention
        if (lane < E_EXP) atomicAdd(&g_psumb[bin * E_EXP + lane], prob);
        if (lane == 0) {
            g_gate[n] = gate;
            g_arg[n]  = arg;
            atomicAdd(&g_zsumb[bin], lse);
        }
    }
}

// =====================================================================
// K2: finish. grid = 64 x 512. Every block replicates the cheap scan
// (L2-hot, no cross-block sync); block b scatters tokens [64b, 64b+64).
// Block 0 also writes the scalars and resets the bins.
// =====================================================================
__global__ void __launch_bounds__(512)
k_finish(float* __restrict__ out) {
    __shared__ int            s_arg[N_TOK];    // 16 KB
    __shared__ float          s_gate[N_TOK];   // 16 KB
    __shared__ unsigned short s_rank[N_TOK];   //  8 KB
    __shared__ int s_cnt[16][E_EXP + 1];
    __shared__ int s_off[16][E_EXP + 1];
    __shared__ int s_tot[E_EXP];

    const int bid  = blockIdx.x;
    const int tid  = threadIdx.x;
    const int w    = tid >> 5;
    const int lane = tid & 31;

    // phase 0: bulk coalesced prefetch (read-only, L2-hot)
    {
        const int4*   pa = reinterpret_cast<const int4*>(g_arg);
        const float4* pg = reinterpret_cast<const float4*>(g_gate);
#pragma unroll
        for (int r = 0; r < 2; r++) {
            int i = tid + r * 512;
            reinterpret_cast<int4*>(s_arg)[i]    = pa[i];
            reinterpret_cast<float4*>(s_gate)[i] = pg[i];
        }
    }
    __syncthreads();

    // phase A: per-chunk expert ranks (warp w owns tokens [256w, 256w+256))
    if (lane <= E_EXP) s_cnt[w][lane] = 0;
    __syncwarp();
#pragma unroll
    for (int g = 0; g < 8; g++) {
        int n = 256 * w + 32 * g + lane;
        int a = s_arg[n];
        unsigned m = __match_any_sync(0xffffffffu, a);
        int prior = s_cnt[w][a];
        __syncwarp();
        if (lane == (int)__ffs(m) - 1) s_cnt[w][a] = prior + __popc(m);
        s_rank[n] = (unsigned short)(prior + __popc(m & ((1u << lane) - 1u)));
        __syncwarp();
    }
    __syncthreads();

    // phase B: exclusive prefix over 16 chunks (warp w = expert w)
    if (lane < 16) {
        int v = s_cnt[lane][w];
        int x = v;
#pragma unroll
        for (int off = 1; off < 16; off <<= 1) {
            int y = __shfl_up_sync(0x0000ffffu, x, off);
            if (lane >= off) x += y;
        }
        s_off[lane][w] = x - v;
        if (lane == 15) s_tot[w] = x;
    }
    __syncthreads();

    // phase C: scatter this block's 64 tokens (one per thread, tid<64)
    if (tid < 64) {
        int n   = 64 * bid + tid;
        int a   = s_arg[n];
        int pos = s_off[n >> 8][a] + (int)s_rank[n];
        if (pos < CCAP) {
            long long off = (long long)n * PLANE + a * CCAP + pos;
            __stcs(out + off, 1.0f);                // dispatch
            __stcs(out + HALF + off, s_gate[n]);    // combine
        }
    }

    // block 0: scalars + bin reset for next graph replay
    if (bid == 0) {
        __shared__ float s_psum[E_EXP];
        __shared__ float s_z;
        if (tid < E_EXP) s_psum[tid] = 0.f;
        if (tid == 0)    s_z = 0.f;
        __syncthreads();
        {
            float v = g_psumb[tid];                 // 512 = NBIN*E_EXP exactly
            g_psumb[tid] = 0.f;
            atomicAdd(&s_psum[tid & (E_EXP - 1)], v);
            if (tid < NBIN) {
                float z = g_zsumb[tid];
                g_zsumb[tid] = 0.f;
                atomicAdd(&s_z, z);
            }
        }
        __syncthreads();
        if (tid == 0) {
            float aux = 0.f;
#pragma unroll
            for (int e = 0; e < E_EXP; e++) aux += s_psum[e] * (float)s_tot[e];
            const float invN = 1.0f / (float)N_TOK;
            out[2 * HALF]     = s_z * invN;                        // z_loss
            out[2 * HALF + 1] = aux * (float)E_EXP * invN * invN;  // aux_loss
        }
    }
}

// ---------------- launch ----------------
extern "C" void kernel_launch(void* const* d_in, const int* in_sizes, int n_in,
                              void* d_out, int out_size) {
    const float* X  = (const float*)d_in[0];
    const float* Wg = (const float*)d_in[1];
    const float* bg = (const float*)d_in[2];
    float* out = (float*)d_out;

    // driver memset node: pure-write zero-fill of both output planes
    cudaMemsetAsync(out, 0, (size_t)(2 * HALF) * sizeof(float));

    k_pool<<<N_TOK / TPB, 512>>>(X, Wg, bg);  // pure-read stream, 4 tokens/block
    k_finish<<<64, 512>>>(out);               // replicated scan + parallel scatter
}

// round 14
// speedup vs baseline: 1.0496x; 1.0496x over previous
#include <cuda_runtime.h>
#include <cstdint>

#define N_TOK   4096
#define C_DIM   64
#define HW      256
#define E_EXP   16
#define CCAP    384
#define PLANE   (E_EXP * CCAP)             /* 6144 */
#define HALF    ((long long)N_TOK * PLANE) /* 25,165,824 floats */
#define NBIN    32

// ---------------- device scratch (bins reset each replay by k_finish blk 0) --------
__device__ float g_gate[N_TOK];
__device__ int   g_arg[N_TOK];
__device__ float g_psumb[NBIN * E_EXP];   // binned prob sums (bin-major)
__device__ float g_zsumb[NBIN];           // binned lse sums

// =====================================================================
// K1: pure-read pool (R12-proven). grid = 4096 x 512. No fences/counters.
// =====================================================================
__global__ void __launch_bounds__(512, 4)
k_pool(const float* __restrict__ X, const float* __restrict__ Wg,
       const float* __restrict__ bg) {
    const int n    = blockIdx.x;
    const int tid  = threadIdx.x;
    const int w    = tid >> 5;
    const int lane = tid & 31;

    __shared__ float s_ch[C_DIM];
    __shared__ float s_w[C_DIM * E_EXP];

    for (int i = tid; i < C_DIM * E_EXP; i += 512) s_w[i] = Wg[i];

    // coalesced streaming read; warp w owns channels [4w, 4w+4)
    const float4* p = reinterpret_cast<const float4*>(X + (size_t)n * C_DIM * HW)
                      + w * 256;
    float part[4] = {0.f, 0.f, 0.f, 0.f};
#pragma unroll
    for (int k = 0; k < 8; k++) {
        float4 v = __ldcs(p + lane + 32 * k);       // lanes consecutive -> coalesced
        part[k >> 1] += (v.x + v.y) + (v.z + v.w);
    }
#pragma unroll
    for (int c = 0; c < 4; c++) {
        float s = part[c];
#pragma unroll
        for (int off = 16; off; off >>= 1) s += __shfl_xor_sync(0xffffffffu, s, off);
        if (lane == 0) s_ch[4 * w + c] = s * (1.0f / HW);
    }
    __syncthreads();

    if (w == 0) {
        float l = -INFINITY;
        if (lane < E_EXP) {
            float acc = bg[lane];
#pragma unroll
            for (int c = 0; c < C_DIM; c++) acc += s_ch[c] * s_w[c * E_EXP + lane];
            l = acc;
        }
        float mx = l;
#pragma unroll
        for (int off = 16; off; off >>= 1) mx = fmaxf(mx, __shfl_xor_sync(0xffffffffu, mx, off));
        float e = (lane < E_EXP) ? __expf(l - mx) : 0.f;
        float s = e;
#pragma unroll
        for (int off = 16; off; off >>= 1) s += __shfl_xor_sync(0xffffffffu, s, off);
        float prob = e / s;
        float lse  = mx + __logf(s);

        unsigned bal = __ballot_sync(0xffffffffu, l == mx);
        int arg = __ffs(bal) - 1;                   // lowest-index max == jnp argmax
        float gate = __shfl_sync(0xffffffffu, prob, arg);

        const int bin = n & (NBIN - 1);             // spread atomic contention 32x
        if (lane < E_EXP) atomicAdd(&g_psumb[bin * E_EXP + lane], prob);
        if (lane == 0) {
            g_gate[n] = gate;
            g_arg[n]  = arg;
            atomicAdd(&g_zsumb[bin], lse);
        }
    }
}

// =====================================================================
// K2: finish. grid = 32 x 1024. 32 warps -> each ranks only 128 tokens
// (4 serial groups instead of 8). Replicated scan, block b scatters
// tokens [128b, 128b+128). Block 0 writes scalars + resets bins.
// =====================================================================
__global__ void __launch_bounds__(1024)
k_finish(float* __restrict__ out) {
    __shared__ int            s_arg[N_TOK];    // 16 KB
    __shared__ unsigned short s_rank[N_TOK];   //  8 KB
    __shared__ int s_cnt[32][E_EXP + 1];       // per-chunk histograms (chunk = 128)
    __shared__ int s_off[32][E_EXP + 1];
    __shared__ int s_tot[E_EXP];

    const int bid  = blockIdx.x;
    const int tid  = threadIdx.x;
    const int w    = tid >> 5;   // 32 warps
    const int lane = tid & 31;

    // phase 0: bulk coalesced prefetch of g_arg (single int4 per thread)
    reinterpret_cast<int4*>(s_arg)[tid] = reinterpret_cast<const int4*>(g_arg)[tid];
    __syncthreads();

    // phase A: warp w ranks tokens [128w, 128w+128) — 4 serial groups
    if (lane <= E_EXP) s_cnt[w][lane] = 0;
    __syncwarp();
#pragma unroll
    for (int g = 0; g < 4; g++) {
        int n = 128 * w + 32 * g + lane;
        int a = s_arg[n];
        unsigned m = __match_any_sync(0xffffffffu, a);
        int prior = s_cnt[w][a];
        __syncwarp();
        if (lane == (int)__ffs(m) - 1) s_cnt[w][a] = prior + __popc(m);
        s_rank[n] = (unsigned short)(prior + __popc(m & ((1u << lane) - 1u)));
        __syncwarp();
    }
    __syncthreads();

    // phase B: exclusive prefix over 32 chunks (warp w < 16 = expert w)
    if (w < E_EXP) {
        int v = s_cnt[lane][w];
        int x = v;
#pragma unroll
        for (int off = 1; off < 32; off <<= 1) {
            int y = __shfl_up_sync(0xffffffffu, x, off);
            if (lane >= off) x += y;
        }
        s_off[lane][w] = x - v;
        if (lane == 31) s_tot[w] = x;
    }
    __syncthreads();

    // phase C: scatter this block's 128 tokens (one per thread, tid<128)
    if (tid < 128) {
        int n   = 128 * bid + tid;
        int a   = s_arg[n];
        int pos = s_off[n >> 7][a] + (int)s_rank[n];
        if (pos < CCAP) {
            long long off = (long long)n * PLANE + a * CCAP + pos;
            float gate = g_gate[n];                 // L2-hit
            __stcs(out + off, 1.0f);                // dispatch
            __stcs(out + HALF + off, gate);         // combine
        }
    }

    // block 0: scalars + bin reset for next graph replay
    if (bid == 0) {
        __shared__ float s_psum[E_EXP];
        __shared__ float s_z;
        if (tid < E_EXP) s_psum[tid] = 0.f;
        if (tid == 0)    s_z = 0.f;
        __syncthreads();
        if (tid < NBIN * E_EXP) {                   // 512 entries
            float v = g_psumb[tid];
            g_psumb[tid] = 0.f;
            atomicAdd(&s_psum[tid & (E_EXP - 1)], v);
            if (tid < NBIN) {
                float z = g_zsumb[tid];
                g_zsumb[tid] = 0.f;
                atomicAdd(&s_z, z);
            }
        }
        __syncthreads();
        if (tid == 0) {
            float aux = 0.f;
#pragma unroll
            for (int e = 0; e < E_EXP; e++) aux += s_psum[e] * (float)s_tot[e];
            const float invN = 1.0f / (float)N_TOK;
            out[2 * HALF]     = s_z * invN;                        // z_loss
            out[2 * HALF + 1] = aux * (float)E_EXP * invN * invN;  // aux_loss
        }
    }
}

// ---------------- launch ----------------
extern "C" void kernel_launch(void* const* d_in, const int* in_sizes, int n_in,
                              void* d_out, int out_size) {
    const float* X  = (const float*)d_in[0];
    const float* Wg = (const float*)d_in[1];
    const float* bg = (const float*)d_in[2];
    float* out = (float*)d_out;

    // driver memset node: pure-write zero-fill of both output planes
    cudaMemsetAsync(out, 0, (size_t)(2 * HALF) * sizeof(float));

    k_pool<<<N_TOK, 512>>>(X, Wg, bg);   // pure-read stream (R12-proven)
    k_finish<<<32, 1024>>>(out);         // halved scan chain + parallel scatter
}